// round 6
// baseline (speedup 1.0000x reference)
#include <cuda_runtime.h>
#include <stdint.h>

// Problem constants (from reference): N_NODES=100000, N_EDGES=3200000
#define NMAX 100000
#define EMAX 3200000

// Scratch: device globals (no allocation allowed in kernel_launch)
__device__ float2 g_v[NMAX];            // (vm*cos(va), vm*sin(va)) per node
__device__ float4 g_acc4[NMAX / 2];     // (p_imb,q_imb) pairs, float4-aliased for reduce

// ---------------------------------------------------------------------------
// K1: per-node masked select + trig precompute + init accumulators.
// Loads staged through shared memory so all global reads are coalesced.
// Mask dtype probed per block (16 int32 words all in {0,1} <=> int32 mask;
// byte-bool misread as int32 passes w.p. 1/8 per word -> 8^-16 misdetect).
// cols: VM=0 VA=1 PG=2 QG=3 PD=4 QD=5
// ---------------------------------------------------------------------------
__global__ void node_prep_kernel(const float* __restrict__ pred,
                                 const float* __restrict__ target,
                                 const void* __restrict__ mask_raw,
                                 float* __restrict__ out,
                                 int n)
{
    __shared__ float sp[256 * 6];
    __shared__ float st[256 * 6];
    __shared__ int   sm[256 * 6];

    // mask dtype probe (uniform across grid)
    bool ok = true;
    if (threadIdx.x < 16) {
        int v = ((const int*)mask_raw)[threadIdx.x];
        ok = (v == 0 || v == 1);
    }
    int mask_is32 = __syncthreads_and(ok);

    int base = blockIdx.x * 256;                 // first node of this block
    int cnt  = n - base; if (cnt > 256) cnt = 256;
    int nf   = cnt * 6;                          // floats this block touches

    // coalesced staging
    for (int j = threadIdx.x; j < nf; j += 256) {
        sp[j] = pred[(size_t)base * 6 + j];
        st[j] = target[(size_t)base * 6 + j];
    }
    if (mask_is32) {
        const int* mm = (const int*)mask_raw + (size_t)base * 6;
        for (int j = threadIdx.x; j < nf; j += 256) sm[j] = mm[j];
    } else {
        const unsigned char* mm = (const unsigned char*)mask_raw + (size_t)base * 6;
        for (int j = threadIdx.x; j < nf; j += 256) sm[j] = mm[j];
    }
    __syncthreads();

    if (blockIdx.x == 0 && threadIdx.x == 0) out[0] = 0.0f;

    int li = threadIdx.x;
    int i  = base + li;
    if (li >= cnt) return;

    float v[6];
#pragma unroll
    for (int k = 0; k < 6; k++) {
        int j = li * 6 + k;
        v[k] = sm[j] ? sp[j] : st[j];
    }

    float s, c;
    sincosf(v[1], &s, &c);                        // precise; only n ops total
    g_v[i] = make_float2(v[0] * c, v[0] * s);     // u = vm * e^{i va}

    float2* acc = (float2*)g_acc4;
    acc[i] = make_float2(v[2] - v[4], v[3] - v[5]);
}

// ---------------------------------------------------------------------------
// K2: 4 edges per thread. All 8 node gathers issued up-front for MLP, then
// pure-FMA flow math (no MUFU), one red.global.add.v2.f32 per edge.
//   vv*cos(dva) = xs*xd + ys*yd ;  vv*sin(dva) = ys*xd - xs*yd
// Edge-index dtype probed per block (JAX demotes int64->int32 unless x64).
// ---------------------------------------------------------------------------
__global__ void edge_kernel(const void* __restrict__ ei_raw,
                            const float* __restrict__ ea,
                            int E, int n)
{
    bool ok = true;
    if (threadIdx.x < 16) {
        long long v = ((const long long*)ei_raw)[threadIdx.x];
        ok = (v >= 0 && v < (long long)n);
    }
    int is64 = __syncthreads_and(ok);

    int e = (blockIdx.x * blockDim.x + threadIdx.x) * 4;
    if (e >= E) return;

    float2* acc = (float2*)g_acc4;

    if (e + 3 < E) {
        int s[4], d[4];
        if (is64) {
            const long long* ei = (const long long*)ei_raw;
            longlong2 s01 = *(const longlong2*)(ei + e);
            longlong2 s23 = *(const longlong2*)(ei + e + 2);
            longlong2 d01 = *(const longlong2*)(ei + E + e);
            longlong2 d23 = *(const longlong2*)(ei + E + e + 2);
            s[0] = (int)s01.x; s[1] = (int)s01.y; s[2] = (int)s23.x; s[3] = (int)s23.y;
            d[0] = (int)d01.x; d[1] = (int)d01.y; d[2] = (int)d23.x; d[3] = (int)d23.y;
        } else {
            const int* ei = (const int*)ei_raw;
            int4 sv = *(const int4*)(ei + e);
            int4 dv = *(const int4*)(ei + E + e);
            s[0] = sv.x; s[1] = sv.y; s[2] = sv.z; s[3] = sv.w;
            d[0] = dv.x; d[1] = dv.y; d[2] = dv.z; d[3] = dv.w;
        }
        float4 gb01 = *(const float4*)(ea + (size_t)e * 2);
        float4 gb23 = *(const float4*)(ea + (size_t)e * 2 + 4);

        // issue all gathers first (independent -> high MLP)
        float2 us[4], ud[4];
#pragma unroll
        for (int k = 0; k < 4; k++) us[k] = __ldg(&g_v[s[k]]);
#pragma unroll
        for (int k = 0; k < 4; k++) ud[k] = __ldg(&g_v[d[k]]);

        float gg[4] = {gb01.x, gb01.z, gb23.x, gb23.z};
        float bb[4] = {gb01.y, gb01.w, gb23.y, gb23.w};

#pragma unroll
        for (int k = 0; k < 4; k++) {
            float vvc = us[k].x * ud[k].x + us[k].y * ud[k].y;
            float vvs = us[k].y * ud[k].x - us[k].x * ud[k].y;
            float pf = gg[k] * vvc + bb[k] * vvs;
            float qf = gg[k] * vvs - bb[k] * vvc;
            asm volatile("red.global.add.v2.f32 [%0], {%1, %2};"
                         :: "l"(&acc[s[k]]), "f"(-pf), "f"(-qf)
                         : "memory");
        }
    } else {
        for (int k = e; k < E; k++) {
            int s0, d0;
            if (is64) {
                const long long* ei = (const long long*)ei_raw;
                s0 = (int)ei[k];
                d0 = (int)ei[E + k];
            } else {
                const int* ei = (const int*)ei_raw;
                s0 = ei[k];
                d0 = ei[E + k];
            }
            float gg = ea[(size_t)k * 2];
            float bb = ea[(size_t)k * 2 + 1];
            float2 us = __ldg(&g_v[s0]);
            float2 ud = __ldg(&g_v[d0]);
            float vvc = us.x * ud.x + us.y * ud.y;
            float vvs = us.y * ud.x - us.x * ud.y;
            float pf = gg * vvc + bb * vvs;
            float qf = gg * vvs - bb * vvc;
            asm volatile("red.global.add.v2.f32 [%0], {%1, %2};"
                         :: "l"(&acc[s0]), "f"(-pf), "f"(-qf)
                         : "memory");
        }
    }
}

// ---------------------------------------------------------------------------
// K3: sum of squares, scaled by 1/n, atomically added into out[0]
// (zeroed by node_prep earlier in the stream). One float4 per thread.
// ---------------------------------------------------------------------------
__global__ void reduce_kernel(float* __restrict__ out, int n)
{
    int nq = n / 2;   // float4 count (n even)
    int i = blockIdx.x * blockDim.x + threadIdx.x;

    float sum = 0.0f;
    if (i < nq) {
        float4 a = g_acc4[i];
        sum = a.x * a.x + a.y * a.y + a.z * a.z + a.w * a.w;
    }

#pragma unroll
    for (int off = 16; off > 0; off >>= 1)
        sum += __shfl_down_sync(0xFFFFFFFFu, sum, off);

    __shared__ float warp_sums[32];
    int lane = threadIdx.x & 31;
    int wid  = threadIdx.x >> 5;
    if (lane == 0) warp_sums[wid] = sum;
    __syncthreads();

    int nwarps = (blockDim.x + 31) >> 5;
    if (wid == 0) {
        float bsum = (lane < nwarps) ? warp_sums[lane] : 0.0f;
#pragma unroll
        for (int off = 16; off > 0; off >>= 1)
            bsum += __shfl_down_sync(0xFFFFFFFFu, bsum, off);
        if (lane == 0)
            atomicAdd(out, bsum / (float)n);
    }
}

extern "C" void kernel_launch(void* const* d_in, const int* in_sizes, int n_in,
                              void* d_out, int out_size)
{
    const float* pred       = (const float*)d_in[0];
    const float* target     = (const float*)d_in[1];
    const void*  edge_index = d_in[2];
    const float* edge_attr  = (const float*)d_in[3];
    const void*  mask       = d_in[4];

    int n = in_sizes[0] / 6;       // nodes
    int E = in_sizes[2] / 2;       // edges
    if (n > NMAX) n = NMAX;
    if (E > EMAX) E = EMAX;

    float* out = (float*)d_out;

    const int B = 256;
    node_prep_kernel<<<(n + B - 1) / B, B>>>(pred, target, mask, out, n);
    int equads = (E + 3) / 4;
    edge_kernel<<<(equads + B - 1) / B, B>>>(edge_index, edge_attr, E, n);
    int nq = n / 2;
    reduce_kernel<<<(nq + B - 1) / B, B>>>(out, n);
}

// round 7
// speedup vs baseline: 1.0066x; 1.0066x over previous
#include <cuda_runtime.h>
#include <stdint.h>

// Problem constants (from reference): N_NODES=100000, N_EDGES=3200000
#define NMAX 100000
#define EMAX 3200000

// Scratch: device globals (no allocation allowed in kernel_launch)
__device__ float2 g_v[NMAX];            // (vm*cos(va), vm*sin(va)) per node
__device__ float4 g_acc4[NMAX / 2];     // (p_imb,q_imb) pairs, float4-aliased for reduce

// ---------------------------------------------------------------------------
// K1: per-node masked select + trig precompute + init accumulators.
// 2 nodes per thread = 12 floats = 3 aligned float4 loads per array.
// No smem, no staging sync. Mask dtype probed per block (16 int32 words all
// in {0,1} <=> int32 mask; byte-bool misread passes w.p. 1/8/word -> 8^-16).
// cols: VM=0 VA=1 PG=2 QG=3 PD=4 QD=5
// ---------------------------------------------------------------------------
__global__ void node_prep_kernel(const float4* __restrict__ pred4,
                                 const float4* __restrict__ target4,
                                 const void* __restrict__ mask_raw,
                                 float* __restrict__ out,
                                 int n)
{
    // mask dtype probe (uniform across grid)
    bool okp = true;
    if (threadIdx.x < 16) {
        int v = ((const int*)mask_raw)[threadIdx.x];
        okp = (v == 0 || v == 1);
    }
    int mask_is32 = __syncthreads_and(okp);

    int j = blockIdx.x * blockDim.x + threadIdx.x;   // pair index
    if (j == 0) out[0] = 0.0f;
    int i0 = j * 2;
    if (i0 >= n) return;
    bool have2 = (i0 + 1 < n);

    // 3 x float4 = 12 floats = rows i0, i0+1
    float4 p0 = pred4[3 * j];
    float4 p1 = pred4[3 * j + 1];
    float4 p2 = have2 ? pred4[3 * j + 2] : make_float4(0.f, 0.f, 0.f, 0.f);
    float4 t0 = target4[3 * j];
    float4 t1 = target4[3 * j + 1];
    float4 t2 = have2 ? target4[3 * j + 2] : make_float4(0.f, 0.f, 0.f, 0.f);

    float pv[12] = {p0.x, p0.y, p0.z, p0.w, p1.x, p1.y,
                    p1.z, p1.w, p2.x, p2.y, p2.z, p2.w};
    float tv[12] = {t0.x, t0.y, t0.z, t0.w, t1.x, t1.y,
                    t1.z, t1.w, t2.x, t2.y, t2.z, t2.w};

    int m[12];
    if (mask_is32) {
        const int4* mm4 = (const int4*)mask_raw;
        int4 m0 = mm4[3 * j];
        int4 m1 = mm4[3 * j + 1];
        int4 m2 = have2 ? mm4[3 * j + 2] : make_int4(0, 0, 0, 0);
        m[0] = m0.x; m[1] = m0.y; m[2]  = m0.z; m[3]  = m0.w;
        m[4] = m1.x; m[5] = m1.y; m[6]  = m1.z; m[7]  = m1.w;
        m[8] = m2.x; m[9] = m2.y; m[10] = m2.z; m[11] = m2.w;
    } else {
        // byte bools: 12 bytes = 3 aligned uint words
        const uint32_t* mmw = (const uint32_t*)mask_raw;
        uint32_t w0 = mmw[3 * j];
        uint32_t w1 = mmw[3 * j + 1];
        uint32_t w2 = have2 ? mmw[3 * j + 2] : 0u;
#pragma unroll
        for (int k = 0; k < 4; k++) {
            m[k]     = (w0 >> (8 * k)) & 0xFF;
            m[4 + k] = (w1 >> (8 * k)) & 0xFF;
            m[8 + k] = (w2 >> (8 * k)) & 0xFF;
        }
    }

    float v[12];
#pragma unroll
    for (int k = 0; k < 12; k++) v[k] = m[k] ? pv[k] : tv[k];

    float2* acc = (float2*)g_acc4;

    {   // node i0: v[0..5]
        float s, c;
        sincosf(v[1], &s, &c);
        g_v[i0]  = make_float2(v[0] * c, v[0] * s);
        acc[i0]  = make_float2(v[2] - v[4], v[3] - v[5]);
    }
    if (have2) {   // node i0+1: v[6..11]
        float s, c;
        sincosf(v[7], &s, &c);
        g_v[i0 + 1] = make_float2(v[6] * c, v[6] * s);
        acc[i0 + 1] = make_float2(v[8] - v[10], v[9] - v[11]);
    }
}

// ---------------------------------------------------------------------------
// K2: 4 edges per thread. All 8 node gathers issued up-front for MLP, then
// pure-FMA flow math (no MUFU), one red.global.add.v2.f32 per edge.
//   vv*cos(dva) = xs*xd + ys*yd ;  vv*sin(dva) = ys*xd - xs*yd
// Edge-index dtype probed per block (JAX demotes int64->int32 unless x64).
// ---------------------------------------------------------------------------
__global__ void edge_kernel(const void* __restrict__ ei_raw,
                            const float* __restrict__ ea,
                            int E, int n)
{
    bool ok = true;
    if (threadIdx.x < 16) {
        long long v = ((const long long*)ei_raw)[threadIdx.x];
        ok = (v >= 0 && v < (long long)n);
    }
    int is64 = __syncthreads_and(ok);

    int e = (blockIdx.x * blockDim.x + threadIdx.x) * 4;
    if (e >= E) return;

    float2* acc = (float2*)g_acc4;

    if (e + 3 < E) {
        int s[4], d[4];
        if (is64) {
            const long long* ei = (const long long*)ei_raw;
            longlong2 s01 = *(const longlong2*)(ei + e);
            longlong2 s23 = *(const longlong2*)(ei + e + 2);
            longlong2 d01 = *(const longlong2*)(ei + E + e);
            longlong2 d23 = *(const longlong2*)(ei + E + e + 2);
            s[0] = (int)s01.x; s[1] = (int)s01.y; s[2] = (int)s23.x; s[3] = (int)s23.y;
            d[0] = (int)d01.x; d[1] = (int)d01.y; d[2] = (int)d23.x; d[3] = (int)d23.y;
        } else {
            const int* ei = (const int*)ei_raw;
            int4 sv = *(const int4*)(ei + e);
            int4 dv = *(const int4*)(ei + E + e);
            s[0] = sv.x; s[1] = sv.y; s[2] = sv.z; s[3] = sv.w;
            d[0] = dv.x; d[1] = dv.y; d[2] = dv.z; d[3] = dv.w;
        }
        float4 gb01 = *(const float4*)(ea + (size_t)e * 2);
        float4 gb23 = *(const float4*)(ea + (size_t)e * 2 + 4);

        // issue all gathers first (independent -> high MLP)
        float2 us[4], ud[4];
#pragma unroll
        for (int k = 0; k < 4; k++) us[k] = __ldg(&g_v[s[k]]);
#pragma unroll
        for (int k = 0; k < 4; k++) ud[k] = __ldg(&g_v[d[k]]);

        float gg[4] = {gb01.x, gb01.z, gb23.x, gb23.z};
        float bb[4] = {gb01.y, gb01.w, gb23.y, gb23.w};

#pragma unroll
        for (int k = 0; k < 4; k++) {
            float vvc = us[k].x * ud[k].x + us[k].y * ud[k].y;
            float vvs = us[k].y * ud[k].x - us[k].x * ud[k].y;
            float pf = gg[k] * vvc + bb[k] * vvs;
            float qf = gg[k] * vvs - bb[k] * vvc;
            asm volatile("red.global.add.v2.f32 [%0], {%1, %2};"
                         :: "l"(&acc[s[k]]), "f"(-pf), "f"(-qf)
                         : "memory");
        }
    } else {
        for (int k = e; k < E; k++) {
            int s0, d0;
            if (is64) {
                const long long* ei = (const long long*)ei_raw;
                s0 = (int)ei[k];
                d0 = (int)ei[E + k];
            } else {
                const int* ei = (const int*)ei_raw;
                s0 = ei[k];
                d0 = ei[E + k];
            }
            float gg = ea[(size_t)k * 2];
            float bb = ea[(size_t)k * 2 + 1];
            float2 us = __ldg(&g_v[s0]);
            float2 ud = __ldg(&g_v[d0]);
            float vvc = us.x * ud.x + us.y * ud.y;
            float vvs = us.y * ud.x - us.x * ud.y;
            float pf = gg * vvc + bb * vvs;
            float qf = gg * vvs - bb * vvc;
            asm volatile("red.global.add.v2.f32 [%0], {%1, %2};"
                         :: "l"(&acc[s0]), "f"(-pf), "f"(-qf)
                         : "memory");
        }
    }
}

// ---------------------------------------------------------------------------
// K3: sum of squares, scaled by 1/n, atomically added into out[0]
// (zeroed by node_prep earlier in the stream). One float4 per thread.
// ---------------------------------------------------------------------------
__global__ void reduce_kernel(float* __restrict__ out, int n)
{
    int nq = n / 2;   // float4 count (n even)
    int i = blockIdx.x * blockDim.x + threadIdx.x;

    float sum = 0.0f;
    if (i < nq) {
        float4 a = g_acc4[i];
        sum = a.x * a.x + a.y * a.y + a.z * a.z + a.w * a.w;
    }

#pragma unroll
    for (int off = 16; off > 0; off >>= 1)
        sum += __shfl_down_sync(0xFFFFFFFFu, sum, off);

    __shared__ float warp_sums[32];
    int lane = threadIdx.x & 31;
    int wid  = threadIdx.x >> 5;
    if (lane == 0) warp_sums[wid] = sum;
    __syncthreads();

    int nwarps = (blockDim.x + 31) >> 5;
    if (wid == 0) {
        float bsum = (lane < nwarps) ? warp_sums[lane] : 0.0f;
#pragma unroll
        for (int off = 16; off > 0; off >>= 1)
            bsum += __shfl_down_sync(0xFFFFFFFFu, bsum, off);
        if (lane == 0)
            atomicAdd(out, bsum / (float)n);
    }
}

extern "C" void kernel_launch(void* const* d_in, const int* in_sizes, int n_in,
                              void* d_out, int out_size)
{
    const float* pred       = (const float*)d_in[0];
    const float* target     = (const float*)d_in[1];
    const void*  edge_index = d_in[2];
    const float* edge_attr  = (const float*)d_in[3];
    const void*  mask       = d_in[4];

    int n = in_sizes[0] / 6;       // nodes
    int E = in_sizes[2] / 2;       // edges
    if (n > NMAX) n = NMAX;
    if (E > EMAX) E = EMAX;

    float* out = (float*)d_out;

    const int B = 256;
    int npairs = (n + 1) / 2;
    node_prep_kernel<<<(npairs + B - 1) / B, B>>>((const float4*)pred,
                                                  (const float4*)target,
                                                  mask, out, n);
    int equads = (E + 3) / 4;
    edge_kernel<<<(equads + B - 1) / B, B>>>(edge_index, edge_attr, E, n);
    int nq = n / 2;
    reduce_kernel<<<(nq + B - 1) / B, B>>>(out, n);
}